// round 8
// baseline (speedup 1.0000x reference)
#include <cuda_runtime.h>
#include <cstdint>

#define D_MODEL 1024
#define TPB     256          // each thread owns 4 contiguous channels in phase 2
#define GRID    592          // 148 SMs x 4 CTAs: fully resident single wave
#define MAXTOK  64           // ceil(32768/592)=56

__device__ float    g_A[D_MODEL];
__device__ float    g_B[D_MODEL];
__device__ float    g_C[D_MODEL];
__device__ unsigned g_bar = 0;   // monotonic grid-barrier ticket counter

// ---------------------------------------------------------------------------
// Single-launch kernel with a software grid barrier.
//
// Linear(12->1024) over the polynomial feature map
//   feats = [t^2, t, t+1, t^2, 2t+2, -1, t^2, 0, 2t+1, t^2, 2t+1, 0]
// collapses per channel d to out[tok][d] = A[d]*t^2 + B[d]*t + C[d]:
//   A = w0+w3+w6+w9
//   B = w1+w2+2*(w4+w8+w10)
//   C = w2+2*w4-w5+w8+w10 + b
//
// Phase 1: blocks 0..3 compute A/B/C (one 48KB W read TOTAL for the grid).
// Barrier: monotonic ticket counter — replay-safe: graph replays serialize,
//   each launch adds exactly GRID arrivals, so epoch = ticket/GRID is
//   launch-unique and the wait target (epoch+1)*GRID is exact.
// Phase 2: all 592 blocks stream 2xFMA + STG.128 rows at the LTS write cap.
//   Token staging + dtype detection are hoisted BEFORE the barrier.
//
// Residency guarantee (no-deadlock): 592 = 148x4 CTAs, __launch_bounds__
// (256, 4), ~40 regs, ~300B smem -> all CTAs of the wave co-resident.
//
// dtype detection (int64 vs int32 tokens): probe first 16 odd 32-bit words;
// little-endian int64 values < 32000 have all-zero high halves
// (P(false positive for int32) ~ 32000^-16).
// ---------------------------------------------------------------------------
__global__ __launch_bounds__(TPB, 4)
void n2_embed_onekernel(const void* __restrict__ ntok_raw,
                        const float* __restrict__ W,
                        const float* __restrict__ b,
                        float4* __restrict__ out,
                        int n_tok) {
    __shared__ float s_t[MAXTOK];
    __shared__ int   s_is64;

    const int tid = threadIdx.x;
    const int bid = blockIdx.x;
    const int*  pi  = (const int*)ntok_raw;
    const int2* pi2 = (const int2*)ntok_raw;

    // ---- dtype detection (warp 0, L2-broadcast probes) ----
    if (tid < 32) {
        int probe = (tid < 16) ? pi[2 * tid + 1] : 0;
        unsigned any = __ballot_sync(0xFFFFFFFFu, probe != 0);
        if (tid == 0) s_is64 = (any == 0) ? 1 : 0;
    }

    // ---- balanced contiguous token partition ----
    const int grid  = gridDim.x;
    const int q     = n_tok / grid;
    const int rem   = n_tok - q * grid;
    const int base  = q * bid + min(bid, rem);
    const int count = q + (bid < rem ? 1 : 0);

    __syncthreads();   // s_is64 visible

    // ---- stage this block's tokens (independent of coefficients) ----
    if (tid < count) {
        int idx = base + tid;
        s_t[tid] = s_is64 ? (float)pi2[idx].x : (float)pi[idx];
    }

    // ---- phase 1: blocks 0..3 compute the coefficient tables ----
    if (bid < 4) {
        int d = (bid << 8) + tid;                 // 4 * 256 = 1024 channels
        const float* w = W + (size_t)d * 12;
        float w0 = w[0], w1 = w[1], w2 = w[2], w3 = w[3];
        float w4 = w[4], w5 = w[5], w6 = w[6];
        float w8 = w[8], w9 = w[9], w10 = w[10];
        g_A[d] = w0 + w3 + w6 + w9;
        g_B[d] = w1 + w2 + 2.0f * (w4 + w8 + w10);
        g_C[d] = w2 + 2.0f * w4 - w5 + w8 + w10 + b[d];
        __threadfence();                          // publish before arrival
    }

    // ---- software grid barrier (replay-safe monotonic tickets) ----
    __syncthreads();                              // whole block done w/ phase 1
    if (tid == 0) {
        unsigned ticket = atomicAdd(&g_bar, 1u);
        unsigned target = (ticket / (unsigned)GRID + 1u) * (unsigned)GRID;
        volatile unsigned* p = &g_bar;            // plain L2 reads, no RMW storm
        while (*p < target) __nanosleep(64);
    }
    __syncthreads();                              // release to whole block

    // ---- phase 2: per-thread coefficients (L2-hot) + streaming stores ----
    const int dbase = tid * 4;
    const float4 A = *(const float4*)&g_A[dbase];
    const float4 B = *(const float4*)&g_B[dbase];
    const float4 C = *(const float4*)&g_C[dbase];

    const int row_f4 = D_MODEL / 4;               // 256 float4 per token row
    float4* outp = out + (size_t)base * row_f4 + tid;

#pragma unroll 4
    for (int k = 0; k < count; k++) {
        float t = s_t[k];
        float4 o;
        o.x = fmaf(fmaf(A.x, t, B.x), t, C.x);
        o.y = fmaf(fmaf(A.y, t, B.y), t, C.y);
        o.z = fmaf(fmaf(A.z, t, B.z), t, C.z);
        o.w = fmaf(fmaf(A.w, t, B.w), t, C.w);
        __stcs(outp, o);                          // evict-first: never re-read
        outp += row_f4;
    }
}

extern "C" void kernel_launch(void* const* d_in, const int* in_sizes, int n_in,
                              void* d_out, int out_size) {
    const void*  ntok = d_in[0];                 // int64 or int32 tokens [B*S]
    const float* W    = (const float*)d_in[1];   // [D_MODEL, 12] row-major
    const float* b    = (const float*)d_in[2];   // [D_MODEL]
    float4* out = (float4*)d_out;

    int n_tok = in_sizes[0];                     // 32768

    n2_embed_onekernel<<<GRID, TPB>>>(ntok, W, b, out, n_tok);
}

// round 9
// speedup vs baseline: 1.0088x; 1.0088x over previous
#include <cuda_runtime.h>
#include <cstdint>

#define D_MODEL 1024
#define TPB     256          // each thread owns 4 contiguous channels
#define GRID    592          // 148 SMs x 4 CTAs: fully resident single wave
#define MAXTOK  64           // ceil(32768/592) = 56

// ---------------------------------------------------------------------------
// Single fused kernel, no inter-block dependency.
//
// Linear(12->1024) over the polynomial feature map
//   feats = [t^2, t, t+1, t^2, 2t+2, -1, t^2, 0, 2t+1, t^2, 2t+1, 0]
// collapses per channel d to out[tok][d] = A[d]*t^2 + B[d]*t + C[d]:
//   A = w0+w3+w6+w9
//   B = w1+w2+2*(w4+w8+w10)
//   C = w2+2*w4-w5+w8+w10 + b
//
// Each thread derives its 4 channels' A/B/C from W directly (13 __ldg loads,
// ~30 FMAs) — every CTA reads the SAME 48KB of W, so the 4 co-resident
// CTAs/SM dedupe in L1 and L2-level W traffic is ~148 x 48KB = 7MB, matching
// the two-kernel variant without its extra launch node.
//
// Grid 592 = 148x4 single wave; balanced contiguous token partition
// (55/56 tokens per block, <2% skew); tokens staged once in SMEM; main loop
// is 2 FMAs + one streaming STG.128 per 4 channels -> LTS write-cap bound.
//
// dtype detection (int64 vs int32 tokens): probe first 16 odd 32-bit words;
// little-endian int64 values < 32000 have all-zero high halves
// (P(false positive for int32) ~ 32000^-16). Reads stay within the first
// 32 int32 words, valid under either dtype.
// ---------------------------------------------------------------------------
__global__ __launch_bounds__(TPB, 4)
void n2_embed_fused592_kernel(const void* __restrict__ ntok_raw,
                              const float* __restrict__ W,
                              const float* __restrict__ b,
                              float4* __restrict__ out,
                              int n_tok) {
    __shared__ float s_t[MAXTOK];
    __shared__ int   s_is64;

    const int tid = threadIdx.x;
    const int bid = blockIdx.x;
    const int*  pi  = (const int*)ntok_raw;
    const int2* pi2 = (const int2*)ntok_raw;

    // ---- dtype detection (warp 0, L2-broadcast probes) ----
    if (tid < 32) {
        int probe = (tid < 16) ? pi[2 * tid + 1] : 0;
        unsigned any = __ballot_sync(0xFFFFFFFFu, probe != 0);
        if (tid == 0) s_is64 = (any == 0) ? 1 : 0;
    }

    // ---- balanced contiguous token partition ----
    const int grid  = gridDim.x;
    const int q     = n_tok / grid;
    const int rem   = n_tok - q * grid;
    const int base  = q * bid + min(bid, rem);
    const int count = q + (bid < rem ? 1 : 0);

    // ---- per-thread coefficients from W (read-only cached loads) ----
    const int dbase = tid * 4;
    const float4* Wv = (const float4*)(W + (size_t)dbase * 12);
    const float4 bias = __ldg((const float4*)(b + dbase));

    float A[4], B[4], C[4];
#pragma unroll
    for (int c4 = 0; c4 < 4; c4++) {
        float4 f0 = __ldg(Wv + 3 * c4 + 0);   // w0 w1 w2 w3
        float4 f1 = __ldg(Wv + 3 * c4 + 1);   // w4 w5 w6 w7
        float4 f2 = __ldg(Wv + 3 * c4 + 2);   // w8 w9 w10 w11
        A[c4] = f0.x + f0.w + f1.z + f2.y;                   // w0+w3+w6+w9
        B[c4] = f0.y + f0.z + 2.0f * (f1.x + f2.x + f2.z);   // w1+w2+2(w4+w8+w10)
        C[c4] = f0.z + 2.0f * f1.x - f1.y + f2.x + f2.z;     // +bias below
    }
    C[0] += bias.x; C[1] += bias.y; C[2] += bias.z; C[3] += bias.w;

    __syncthreads();   // s_is64 visible

    // ---- stage this block's tokens into shared ----
    if (tid < count) {
        int idx = base + tid;
        s_t[tid] = s_is64 ? (float)pi2[idx].x : (float)pi[idx];
    }
    __syncthreads();

    // ---- streaming loop: 2 FMAs + streaming STG.128 per token ----
    const int row_f4 = D_MODEL / 4;               // 256 float4 per token row
    float4* outp = out + (size_t)base * row_f4 + tid;

#pragma unroll 4
    for (int k = 0; k < count; k++) {
        float t = s_t[k];
        float4 o;
        o.x = fmaf(fmaf(A[0], t, B[0]), t, C[0]);
        o.y = fmaf(fmaf(A[1], t, B[1]), t, C[1]);
        o.z = fmaf(fmaf(A[2], t, B[2]), t, C[2]);
        o.w = fmaf(fmaf(A[3], t, B[3]), t, C[3]);
        __stcs(outp, o);                          // evict-first: never re-read
        outp += row_f4;
    }
}

extern "C" void kernel_launch(void* const* d_in, const int* in_sizes, int n_in,
                              void* d_out, int out_size) {
    const void*  ntok = d_in[0];                 // int64 or int32 tokens [B*S]
    const float* W    = (const float*)d_in[1];   // [D_MODEL, 12] row-major
    const float* b    = (const float*)d_in[2];   // [D_MODEL]
    float4* out = (float4*)d_out;

    int n_tok = in_sizes[0];                     // 32768

    n2_embed_fused592_kernel<<<GRID, TPB>>>(ntok, W, b, out, n_tok);
}